// round 13
// baseline (speedup 1.0000x reference)
#include <cuda_runtime.h>
#include <math.h>
#include <stdint.h>

// ---------------------------------------------------------------------------
// CG tensor-product network (LMAX=4, taus=16, t_O=16), B=256.
// Pipeline: k_init (CG coefs + zero stats) -> k_cg (templated fragment
// products, natural order — best measured) -> k_prepw (fold BN into
// pre-broadcast packed weights) -> k_gemm (f32x2 GEMM, 128-ch K-slices,
// 64-n tiles -> 1840 half-cost blocks, 15MB partials) ->
// k_reduce (float4-vectorized).
// ---------------------------------------------------------------------------

#define NT 42

__constant__ int c_tL1[NT] = {0,1,2,3,4, 1,1,2,2,3,3,4,4, 1,2,2,2,3,3,3,4,4,4,
                              2,2,3,3,3,3,4,4,4,4, 2,3,3,3,4,4,4,4,4};
__constant__ int c_tL2[NT] = {0,1,2,3,4, 0,1,1,2,2,3,3,4, 1,0,1,2,1,2,3,2,3,4,
                              1,2,0,1,2,3,1,2,3,4, 2,1,2,3,0,1,2,3,4};

__constant__ int c_chanbase[6]   = {0,1280,3328,5888,8448,10752};
__constant__ int c_N[5]          = {256,768,1280,1792,2304};
__constant__ int c_inoff[5]      = {0,16,64,144,256};
__constant__ int c_TFF[5]        = {1280,2048,2560,2560,2304};
__constant__ int c_woff[5]       = {0,20480,53248,94208,135168};
__constant__ int c_pobase[6]     = {0,8192,32768,73728,131072,204800};
__constant__ int c_xbase[5]      = {0,327680,1900544,5177344,9764864};

// GEMM decomposition: 128-channel K-slices x 64-n tiles
// blocks/l = splits[l] * (Nl/64): 40,192,400,560,648 -> prefix below
__constant__ int c_itemPrefix[6] = {0,40,232,632,1192,1840};
__constant__ int c_splits[5]     = {10,16,20,20,18};
__constant__ int c_pbase2[6]     = {0,81920,475136,1294336,2441216,3768320};

// scratch (static __device__ globals: sanctioned no-alloc scratch path)
__device__ float  g_cg[NT * 81];
__device__ float  g_sumsq[10752];
__device__ float2 g_X[15073280];        // interleaved (xr, xi), [c][m*256+b]
__device__ float4 g_W2[172032];         // [chan][o] -> {wx, wx, -wy, wy}
__device__ float  g_partial[3768320];   // per-l K-slice partials, [o][n][ri]

// -------------------------- f32x2 helpers ----------------------------------
__device__ __forceinline__ void fma2(uint64_t& d, uint64_t a, uint64_t b) {
    asm("fma.rn.f32x2 %0, %1, %2, %0;" : "+l"(d) : "l"(a), "l"(b));
}
__device__ __forceinline__ uint64_t swap32(uint64_t v) {
    uint32_t lo = (uint32_t)v, hi = (uint32_t)(v >> 32);
    uint64_t r;
    asm("mov.b64 %0, {%1, %2};" : "=l"(r) : "r"(hi), "r"(lo));
    return r;
}
__device__ __forceinline__ float2 unpack2(uint64_t v) {
    float2 f;
    asm("mov.b64 {%0, %1}, %2;" : "=f"(f.x), "=f"(f.y) : "l"(v));
    return f;
}

// -------------------------- CG coefficients --------------------------------
__device__ double dfact(int n) {
    double r = 1.0;
    for (int i = 2; i <= n; ++i) r *= (double)i;
    return r;
}

__device__ double cg_coef(int j1, int m1, int j2, int m2, int j, int m) {
    if (m1 + m2 != m) return 0.0;
    double pref = sqrt((2.0 * j + 1.0) * dfact(j + j1 - j2) * dfact(j - j1 + j2)
                       * dfact(j1 + j2 - j) / dfact(j1 + j2 + j + 1));
    pref *= sqrt(dfact(j + m) * dfact(j - m) * dfact(j1 - m1) * dfact(j1 + m1)
               * dfact(j2 - m2) * dfact(j2 + m2));
    double s = 0.0;
    for (int k = 0; k <= j1 + j2 - j; ++k) {
        if (j1 - m1 - k < 0 || j2 + m2 - k < 0 ||
            j - j2 + m1 + k < 0 || j - j1 - m2 + k < 0) continue;
        double term = 1.0 / (dfact(k) * dfact(j1 + j2 - j - k) * dfact(j1 - m1 - k)
                           * dfact(j2 + m2 - k) * dfact(j - j2 + m1 + k)
                           * dfact(j - j1 - m2 + k));
        s += (k & 1) ? -term : term;
    }
    return pref * s;
}

__constant__ int c_tLfull[NT] = {0,0,0,0,0, 1,1,1,1,1,1,1,1, 2,2,2,2,2,2,2,2,2,2,
                                 3,3,3,3,3,3,3,3,3,3, 4,4,4,4,4,4,4,4,4};

__global__ void k_init() {
    int t = blockIdx.x;                        // 42 blocks, 256 threads
    g_sumsq[t * 256 + threadIdx.x] = 0.0f;     // 42*256 == 10752 exactly
    int l = c_tLfull[t], l1 = c_tL1[t], l2 = c_tL2[t];
    int s = l1 + l2 - l;
    for (int e = threadIdx.x; e < 81; e += blockDim.x) {
        int M = e / 9, M1 = e % 9;
        float v = 0.0f;
        if (M <= 2 * l && M1 <= 2 * l1) {
            int M2 = M + s - M1;
            if (M2 >= 0 && M2 <= 2 * l2)
                v = (float)cg_coef(l1, M1 - l1, l2, M2 - l2, l, M - l);
        }
        g_cg[t * 81 + e] = v;
    }
}

// -------------------- CG tensor product (templated math) --------------------
__device__ __forceinline__ int sidx(int ri, int ch, int m, int lane) {
    return ((ri * 16 + ch) * 9 + m) * 16 + lane;
}

template <int L, int L1, int L2, int RANK>
__device__ __forceinline__ void cg_math(const float* __restrict__ sA,
                                        const float* __restrict__ sB,
                                        const float* __restrict__ sC,
                                        int b0) {
    constexpr int D  = 2 * L + 1;
    constexpr int D1 = 2 * L1 + 1;
    constexpr int D2 = 2 * L2 + 1;
    constexpr int S  = L1 + L2 - L;
    constexpr int XB[5] = {0, 327680, 1900544, 5177344, 9764864};
    constexpr int CB[5] = {0, 1280, 3328, 5888, 8448};
    constexpr int NL = 256 * D;

    const int lane = threadIdx.x & 15;   // b within chunk
    const int j    = threadIdx.x >> 4;   // second channel index

    float br[D2], bi[D2];
    #pragma unroll
    for (int m = 0; m < D2; ++m) {
        br[m] = sB[sidx(0, j, m, lane)];
        bi[m] = sB[sidx(1, j, m, lane)];
    }

    for (int i = 0; i < 16; ++i) {
        float ar[D1], ai[D1];
        #pragma unroll
        for (int m = 0; m < D1; ++m) {
            ar[m] = sA[sidx(0, i, m, lane)];
            ai[m] = sA[sidx(1, i, m, lane)];
        }
        int chan = RANK * 256 + i * 16 + j;
        int xb   = XB[L] + chan * NL + b0 + lane;
        float ss = 0.0f;
        #pragma unroll
        for (int M = 0; M < D; ++M) {
            float fr = 0.0f, fi = 0.0f;
            #pragma unroll
            for (int M1 = 0; M1 < D1; ++M1) {
                int M2 = M + S - M1;
                if (M2 >= 0 && M2 <= 2 * L2) {
                    float cg = sC[M * 9 + M1];
                    fr += cg * (ar[M1] * br[M2] - ai[M1] * bi[M2]);
                    fi += cg * (ar[M1] * bi[M2] + ai[M1] * br[M2]);
                }
            }
            g_X[xb + M * 256] = make_float2(fr, fi);
            ss += fr * fr + fi * fi;
        }
        #pragma unroll
        for (int off = 8; off; off >>= 1)
            ss += __shfl_xor_sync(0xffffffffu, ss, off);
        if (lane == 0) atomicAdd(&g_sumsq[CB[L] + chan], ss);
    }
}

// grid: 42 triples * 16 b-chunks; block 256 = (16 j) x (16 b)
__global__ void __launch_bounds__(256) k_cg(const float* __restrict__ Fs) {
    int t  = blockIdx.x >> 4;            // natural triple order (best measured)
    int b0 = (blockIdx.x & 15) << 4;
    int l1 = c_tL1[t], l2 = c_tL2[t];
    int d1 = 2 * l1 + 1, d2 = 2 * l2 + 1;

    __shared__ float sA[2 * 16 * 9 * 16];
    __shared__ float sB[2 * 16 * 9 * 16];
    __shared__ float sC[81];

    for (int e = threadIdx.x; e < 81; e += 256) sC[e] = g_cg[t * 81 + e];

    int off1 = c_inoff[l1], off2 = c_inoff[l2];
    int nA = 32 * d1;
    for (int e = threadIdx.x; e < 16 * nA; e += 256) {
        int bb = e / nA; int r = e - bb * nA;
        int ri = r & 1;  int cm = r >> 1;
        int ch = cm / d1; int mm = cm - ch * d1;
        sA[sidx(ri, ch, mm, bb)] = Fs[(b0 + bb) * 800 + (off1 + ch * d1 + mm) * 2 + ri];
    }
    int nB = 32 * d2;
    for (int e = threadIdx.x; e < 16 * nB; e += 256) {
        int bb = e / nB; int r = e - bb * nB;
        int ri = r & 1;  int cm = r >> 1;
        int ch = cm / d2; int mm = cm - ch * d2;
        sB[sidx(ri, ch, mm, bb)] = Fs[(b0 + bb) * 800 + (off2 + ch * d2 + mm) * 2 + ri];
    }
    __syncthreads();

    switch (t) {
        case  0: cg_math<0,0,0,0>(sA,sB,sC,b0); break;
        case  1: cg_math<0,1,1,1>(sA,sB,sC,b0); break;
        case  2: cg_math<0,2,2,2>(sA,sB,sC,b0); break;
        case  3: cg_math<0,3,3,3>(sA,sB,sC,b0); break;
        case  4: cg_math<0,4,4,4>(sA,sB,sC,b0); break;
        case  5: cg_math<1,1,0,0>(sA,sB,sC,b0); break;
        case  6: cg_math<1,1,1,1>(sA,sB,sC,b0); break;
        case  7: cg_math<1,2,1,2>(sA,sB,sC,b0); break;
        case  8: cg_math<1,2,2,3>(sA,sB,sC,b0); break;
        case  9: cg_math<1,3,2,4>(sA,sB,sC,b0); break;
        case 10: cg_math<1,3,3,5>(sA,sB,sC,b0); break;
        case 11: cg_math<1,4,3,6>(sA,sB,sC,b0); break;
        case 12: cg_math<1,4,4,7>(sA,sB,sC,b0); break;
        case 13: cg_math<2,1,1,0>(sA,sB,sC,b0); break;
        case 14: cg_math<2,2,0,1>(sA,sB,sC,b0); break;
        case 15: cg_math<2,2,1,2>(sA,sB,sC,b0); break;
        case 16: cg_math<2,2,2,3>(sA,sB,sC,b0); break;
        case 17: cg_math<2,3,1,4>(sA,sB,sC,b0); break;
        case 18: cg_math<2,3,2,5>(sA,sB,sC,b0); break;
        case 19: cg_math<2,3,3,6>(sA,sB,sC,b0); break;
        case 20: cg_math<2,4,2,7>(sA,sB,sC,b0); break;
        case 21: cg_math<2,4,3,8>(sA,sB,sC,b0); break;
        case 22: cg_math<2,4,4,9>(sA,sB,sC,b0); break;
        case 23: cg_math<3,2,1,0>(sA,sB,sC,b0); break;
        case 24: cg_math<3,2,2,1>(sA,sB,sC,b0); break;
        case 25: cg_math<3,3,0,2>(sA,sB,sC,b0); break;
        case 26: cg_math<3,3,1,3>(sA,sB,sC,b0); break;
        case 27: cg_math<3,3,2,4>(sA,sB,sC,b0); break;
        case 28: cg_math<3,3,3,5>(sA,sB,sC,b0); break;
        case 29: cg_math<3,4,1,6>(sA,sB,sC,b0); break;
        case 30: cg_math<3,4,2,7>(sA,sB,sC,b0); break;
        case 31: cg_math<3,4,3,8>(sA,sB,sC,b0); break;
        case 32: cg_math<3,4,4,9>(sA,sB,sC,b0); break;
        case 33: cg_math<4,2,2,0>(sA,sB,sC,b0); break;
        case 34: cg_math<4,3,1,1>(sA,sB,sC,b0); break;
        case 35: cg_math<4,3,2,2>(sA,sB,sC,b0); break;
        case 36: cg_math<4,3,3,3>(sA,sB,sC,b0); break;
        case 37: cg_math<4,4,0,4>(sA,sB,sC,b0); break;
        case 38: cg_math<4,4,1,5>(sA,sB,sC,b0); break;
        case 39: cg_math<4,4,2,6>(sA,sB,sC,b0); break;
        case 40: cg_math<4,4,3,7>(sA,sB,sC,b0); break;
        case 41: cg_math<4,4,4,8>(sA,sB,sC,b0); break;
    }
}

// ---------------- fold BN scale into pre-broadcast weights ------------------
__global__ void k_prepw(const float* __restrict__ W) {
    int gid = blockIdx.x * 256 + threadIdx.x;   // 672*256 == 172032 exactly
    int cgl = gid >> 4;
    int o   = gid & 15;
    int l = 0;
    while (l < 4 && cgl >= c_chanbase[l + 1]) ++l;
    int cl = cgl - c_chanbase[l];
    float var   = g_sumsq[cgl] * (1.0f / (256.0f * (float)(2 * l + 1)));
    float scale = 1.0f / (sqrtf(var) + 1e-5f);
    int widx = (c_woff[l] + o * c_TFF[l] + cl) * 2;
    float wr = W[widx + 0] * scale;
    float wi = W[widx + 1] * scale;
    g_W2[gid] = make_float4(wr, wr, -wi, wi);   // {wx, wx, -wy, wy}
}

// -------------------- complex GEMM via packed f32x2 + smem W ----------------
// 1840 half-cost blocks (128 ch x 64 n x 16 o), 6 blocks/SM (32KB smem),
// 15MB partials. Thread tile: 1 n x 8 outputs (8 u64 accs). Inner loop =
// 1 X LDG.64 (pipelined) + 8 warp-uniform LDS.128 + 1 swap + 16 fma2 / ch.
__global__ void __launch_bounds__(128, 6) k_gemm() {
    __shared__ float4 sW[2048];                    // [128 ch][16 o] = 32KB

    int bid = blockIdx.x;
    int l = 0;
    while (l < 4 && bid >= c_itemPrefix[l + 1]) ++l;
    int rel    = bid - c_itemPrefix[l];
    int Nl     = c_N[l];
    int ntiles = Nl >> 6;                          // 64-n tiles
    int ntile  = rel % ntiles;
    int ks     = rel / ntiles;
    int c0     = ks << 7;                          // 128 channels per slice

    // stage W tile (2048 float4 = 32KB), once
    const float4* __restrict__ Wg = g_W2 + (c_chanbase[l] + c0) * 16;
    #pragma unroll
    for (int e = threadIdx.x; e < 2048; e += 128)
        sW[e] = Wg[e];
    __syncthreads();

    int og = (threadIdx.x >> 6) << 3;              // output base: 0 or 8
    int n0 = (ntile << 6) + (threadIdx.x & 63);    // single n per thread

    const uint64_t* __restrict__ X =
        (const uint64_t*)(g_X + (size_t)(c_xbase[l] + c0 * Nl + n0));
    const ulonglong2* __restrict__ Ws = ((const ulonglong2*)sW) + og;

    uint64_t acc[8];                               // (ar,ai) per output
    #pragma unroll
    for (int o = 0; o < 8; ++o) acc[o] = 0ULL;

    #pragma unroll 4
    for (int cc = 0; cc < 128; ++cc) {
        uint64_t x0 = __ldg(X + cc * Nl);
        uint64_t x0s = swap32(x0);
        const ulonglong2* wrow = Ws + cc * 16;
        #pragma unroll
        for (int oo = 0; oo < 8; ++oo) {
            ulonglong2 w = wrow[oo];               // LDS.128 broadcast
            fma2(acc[oo], w.x, x0);
            fma2(acc[oo], w.y, x0s);
        }
    }

    float* P = g_partial + c_pbase2[l] + ks * (Nl << 5);
    #pragma unroll
    for (int oo = 0; oo < 8; ++oo) {
        int o = og + oo;
        float2 a = unpack2(acc[oo]);
        *(float2*)(P + (size_t)(o * Nl + n0) * 2) = a;
    }
}

// -------------------- reduce K-slices into harness layout (float4) ----------
__global__ void k_reduce(float* __restrict__ out) {
    int p4 = blockIdx.x * 256 + threadIdx.x;   // 200*256 == 51200 float4 groups
    int p  = p4 << 2;
    int l = 0;
    while (l < 4 && p >= c_pobase[l + 1]) ++l;
    int rem = p - c_pobase[l];
    int Nl  = c_N[l];
    int stride4 = Nl << 3;                     // (Nl<<5)/4 in float4 units
    const float4* P = (const float4*)(g_partial + c_pbase2[l]) + (rem >> 2);
    int ns = c_splits[l];
    float4 s = make_float4(0.f, 0.f, 0.f, 0.f);
    #pragma unroll 4
    for (int ks = 0; ks < ns; ++ks) {
        float4 v = __ldg(P + ks * stride4);
        s.x += v.x; s.y += v.y; s.z += v.z; s.w += v.w;
    }
    // rem = (o*Nl + n)*2 + ri; group covers (n, ri=0/1) and (n+1, ri=0/1)
    int on = rem >> 1;
    int o  = on / Nl;
    int n  = on - o * Nl;
    int M  = n >> 8, b = n & 255;
    int row = c_inoff[l] + o * (2 * l + 1) + M;
    *(float2*)(out + (size_t)b * 800 + row * 2)       = make_float2(s.x, s.y);
    *(float2*)(out + (size_t)(b + 1) * 800 + row * 2) = make_float2(s.z, s.w);
}

// ---------------------------------------------------------------------------
extern "C" void kernel_launch(void* const* d_in, const int* in_sizes, int n_in,
                              void* d_out, int out_size) {
    const float* Fs = (const float*)d_in[0];
    const float* W  = (const float*)d_in[1];
    if (n_in >= 2 && in_sizes[0] == 344064) {   // defensive: metadata order
        W  = (const float*)d_in[0];
        Fs = (const float*)d_in[1];
    }
    float* out = (float*)d_out;

    k_init  <<<42,   256>>>();
    k_cg    <<<672,  256>>>(Fs);
    k_prepw <<<672,  256>>>(W);
    k_gemm  <<<1840, 128>>>();
    k_reduce<<<200,  256>>>(out);
}

// round 14
// speedup vs baseline: 1.0113x; 1.0113x over previous
#include <cuda_runtime.h>
#include <math.h>
#include <stdint.h>

// ---------------------------------------------------------------------------
// CG tensor-product network (LMAX=4, taus=16, t_O=16), B=256.
// Pipeline: k_init -> k_cg (templated, natural order) -> k_prepw ->
// k_gemm (f32x2 GEMM, 128-ch K-slices x 256-n tiles -> 460 blocks in ONE
// resident wave, thread tile 4n x 8o, 15MB partials) -> k_reduce (float4).
// ---------------------------------------------------------------------------

#define NT 42

__constant__ int c_tL1[NT] = {0,1,2,3,4, 1,1,2,2,3,3,4,4, 1,2,2,2,3,3,3,4,4,4,
                              2,2,3,3,3,3,4,4,4,4, 2,3,3,3,4,4,4,4,4};
__constant__ int c_tL2[NT] = {0,1,2,3,4, 0,1,1,2,2,3,3,4, 1,0,1,2,1,2,3,2,3,4,
                              1,2,0,1,2,3,1,2,3,4, 2,1,2,3,0,1,2,3,4};

__constant__ int c_chanbase[6]   = {0,1280,3328,5888,8448,10752};
__constant__ int c_N[5]          = {256,768,1280,1792,2304};
__constant__ int c_inoff[5]      = {0,16,64,144,256};
__constant__ int c_TFF[5]        = {1280,2048,2560,2560,2304};
__constant__ int c_woff[5]       = {0,20480,53248,94208,135168};
__constant__ int c_pobase[6]     = {0,8192,32768,73728,131072,204800};
__constant__ int c_xbase[5]      = {0,327680,1900544,5177344,9764864};

// GEMM decomposition: 128-channel K-slices x 256-n tiles
// blocks/l = splits[l]*(Nl/256): 10,48,100,140,162 -> 460 total
__constant__ int c_itemPrefix[6] = {0,10,58,158,298,460};
__constant__ int c_splits[5]     = {10,16,20,20,18};
__constant__ int c_pbase2[6]     = {0,81920,475136,1294336,2441216,3768320};

// scratch (static __device__ globals: sanctioned no-alloc scratch path)
__device__ float  g_cg[NT * 81];
__device__ float  g_sumsq[10752];
__device__ float2 g_X[15073280];        // interleaved (xr, xi), [c][m*256+b]
__device__ float4 g_W2[172032];         // [chan][o] -> {wx, wx, -wy, wy}
__device__ float  g_partial[3768320];   // per-l K-slice partials, [o][n][ri]

// -------------------------- f32x2 helpers ----------------------------------
__device__ __forceinline__ void fma2(uint64_t& d, uint64_t a, uint64_t b) {
    asm("fma.rn.f32x2 %0, %1, %2, %0;" : "+l"(d) : "l"(a), "l"(b));
}
__device__ __forceinline__ uint64_t swap32(uint64_t v) {
    uint32_t lo = (uint32_t)v, hi = (uint32_t)(v >> 32);
    uint64_t r;
    asm("mov.b64 %0, {%1, %2};" : "=l"(r) : "r"(hi), "r"(lo));
    return r;
}
__device__ __forceinline__ float2 unpack2(uint64_t v) {
    float2 f;
    asm("mov.b64 {%0, %1}, %2;" : "=f"(f.x), "=f"(f.y) : "l"(v));
    return f;
}

// -------------------------- CG coefficients --------------------------------
__device__ double dfact(int n) {
    double r = 1.0;
    for (int i = 2; i <= n; ++i) r *= (double)i;
    return r;
}

__device__ double cg_coef(int j1, int m1, int j2, int m2, int j, int m) {
    if (m1 + m2 != m) return 0.0;
    double pref = sqrt((2.0 * j + 1.0) * dfact(j + j1 - j2) * dfact(j - j1 + j2)
                       * dfact(j1 + j2 - j) / dfact(j1 + j2 + j + 1));
    pref *= sqrt(dfact(j + m) * dfact(j - m) * dfact(j1 - m1) * dfact(j1 + m1)
               * dfact(j2 - m2) * dfact(j2 + m2));
    double s = 0.0;
    for (int k = 0; k <= j1 + j2 - j; ++k) {
        if (j1 - m1 - k < 0 || j2 + m2 - k < 0 ||
            j - j2 + m1 + k < 0 || j - j1 - m2 + k < 0) continue;
        double term = 1.0 / (dfact(k) * dfact(j1 + j2 - j - k) * dfact(j1 - m1 - k)
                           * dfact(j2 + m2 - k) * dfact(j - j2 + m1 + k)
                           * dfact(j - j1 - m2 + k));
        s += (k & 1) ? -term : term;
    }
    return pref * s;
}

__constant__ int c_tLfull[NT] = {0,0,0,0,0, 1,1,1,1,1,1,1,1, 2,2,2,2,2,2,2,2,2,2,
                                 3,3,3,3,3,3,3,3,3,3, 4,4,4,4,4,4,4,4,4};

__global__ void k_init() {
    int t = blockIdx.x;                        // 42 blocks, 256 threads
    g_sumsq[t * 256 + threadIdx.x] = 0.0f;     // 42*256 == 10752 exactly
    int l = c_tLfull[t], l1 = c_tL1[t], l2 = c_tL2[t];
    int s = l1 + l2 - l;
    for (int e = threadIdx.x; e < 81; e += blockDim.x) {
        int M = e / 9, M1 = e % 9;
        float v = 0.0f;
        if (M <= 2 * l && M1 <= 2 * l1) {
            int M2 = M + s - M1;
            if (M2 >= 0 && M2 <= 2 * l2)
                v = (float)cg_coef(l1, M1 - l1, l2, M2 - l2, l, M - l);
        }
        g_cg[t * 81 + e] = v;
    }
}

// -------------------- CG tensor product (templated math) --------------------
__device__ __forceinline__ int sidx(int ri, int ch, int m, int lane) {
    return ((ri * 16 + ch) * 9 + m) * 16 + lane;
}

template <int L, int L1, int L2, int RANK>
__device__ __forceinline__ void cg_math(const float* __restrict__ sA,
                                        const float* __restrict__ sB,
                                        const float* __restrict__ sC,
                                        int b0) {
    constexpr int D  = 2 * L + 1;
    constexpr int D1 = 2 * L1 + 1;
    constexpr int D2 = 2 * L2 + 1;
    constexpr int S  = L1 + L2 - L;
    constexpr int XB[5] = {0, 327680, 1900544, 5177344, 9764864};
    constexpr int CB[5] = {0, 1280, 3328, 5888, 8448};
    constexpr int NL = 256 * D;

    const int lane = threadIdx.x & 15;   // b within chunk
    const int j    = threadIdx.x >> 4;   // second channel index

    float br[D2], bi[D2];
    #pragma unroll
    for (int m = 0; m < D2; ++m) {
        br[m] = sB[sidx(0, j, m, lane)];
        bi[m] = sB[sidx(1, j, m, lane)];
    }

    for (int i = 0; i < 16; ++i) {
        float ar[D1], ai[D1];
        #pragma unroll
        for (int m = 0; m < D1; ++m) {
            ar[m] = sA[sidx(0, i, m, lane)];
            ai[m] = sA[sidx(1, i, m, lane)];
        }
        int chan = RANK * 256 + i * 16 + j;
        int xb   = XB[L] + chan * NL + b0 + lane;
        float ss = 0.0f;
        #pragma unroll
        for (int M = 0; M < D; ++M) {
            float fr = 0.0f, fi = 0.0f;
            #pragma unroll
            for (int M1 = 0; M1 < D1; ++M1) {
                int M2 = M + S - M1;
                if (M2 >= 0 && M2 <= 2 * L2) {
                    float cg = sC[M * 9 + M1];
                    fr += cg * (ar[M1] * br[M2] - ai[M1] * bi[M2]);
                    fi += cg * (ar[M1] * bi[M2] + ai[M1] * br[M2]);
                }
            }
            g_X[xb + M * 256] = make_float2(fr, fi);
            ss += fr * fr + fi * fi;
        }
        #pragma unroll
        for (int off = 8; off; off >>= 1)
            ss += __shfl_xor_sync(0xffffffffu, ss, off);
        if (lane == 0) atomicAdd(&g_sumsq[CB[L] + chan], ss);
    }
}

// grid: 42 triples * 16 b-chunks; block 256 = (16 j) x (16 b)
__global__ void __launch_bounds__(256) k_cg(const float* __restrict__ Fs) {
    int t  = blockIdx.x >> 4;            // natural triple order (best measured)
    int b0 = (blockIdx.x & 15) << 4;
    int l1 = c_tL1[t], l2 = c_tL2[t];
    int d1 = 2 * l1 + 1, d2 = 2 * l2 + 1;

    __shared__ float sA[2 * 16 * 9 * 16];
    __shared__ float sB[2 * 16 * 9 * 16];
    __shared__ float sC[81];

    for (int e = threadIdx.x; e < 81; e += 256) sC[e] = g_cg[t * 81 + e];

    int off1 = c_inoff[l1], off2 = c_inoff[l2];
    int nA = 32 * d1;
    for (int e = threadIdx.x; e < 16 * nA; e += 256) {
        int bb = e / nA; int r = e - bb * nA;
        int ri = r & 1;  int cm = r >> 1;
        int ch = cm / d1; int mm = cm - ch * d1;
        sA[sidx(ri, ch, mm, bb)] = Fs[(b0 + bb) * 800 + (off1 + ch * d1 + mm) * 2 + ri];
    }
    int nB = 32 * d2;
    for (int e = threadIdx.x; e < 16 * nB; e += 256) {
        int bb = e / nB; int r = e - bb * nB;
        int ri = r & 1;  int cm = r >> 1;
        int ch = cm / d2; int mm = cm - ch * d2;
        sB[sidx(ri, ch, mm, bb)] = Fs[(b0 + bb) * 800 + (off2 + ch * d2 + mm) * 2 + ri];
    }
    __syncthreads();

    switch (t) {
        case  0: cg_math<0,0,0,0>(sA,sB,sC,b0); break;
        case  1: cg_math<0,1,1,1>(sA,sB,sC,b0); break;
        case  2: cg_math<0,2,2,2>(sA,sB,sC,b0); break;
        case  3: cg_math<0,3,3,3>(sA,sB,sC,b0); break;
        case  4: cg_math<0,4,4,4>(sA,sB,sC,b0); break;
        case  5: cg_math<1,1,0,0>(sA,sB,sC,b0); break;
        case  6: cg_math<1,1,1,1>(sA,sB,sC,b0); break;
        case  7: cg_math<1,2,1,2>(sA,sB,sC,b0); break;
        case  8: cg_math<1,2,2,3>(sA,sB,sC,b0); break;
        case  9: cg_math<1,3,2,4>(sA,sB,sC,b0); break;
        case 10: cg_math<1,3,3,5>(sA,sB,sC,b0); break;
        case 11: cg_math<1,4,3,6>(sA,sB,sC,b0); break;
        case 12: cg_math<1,4,4,7>(sA,sB,sC,b0); break;
        case 13: cg_math<2,1,1,0>(sA,sB,sC,b0); break;
        case 14: cg_math<2,2,0,1>(sA,sB,sC,b0); break;
        case 15: cg_math<2,2,1,2>(sA,sB,sC,b0); break;
        case 16: cg_math<2,2,2,3>(sA,sB,sC,b0); break;
        case 17: cg_math<2,3,1,4>(sA,sB,sC,b0); break;
        case 18: cg_math<2,3,2,5>(sA,sB,sC,b0); break;
        case 19: cg_math<2,3,3,6>(sA,sB,sC,b0); break;
        case 20: cg_math<2,4,2,7>(sA,sB,sC,b0); break;
        case 21: cg_math<2,4,3,8>(sA,sB,sC,b0); break;
        case 22: cg_math<2,4,4,9>(sA,sB,sC,b0); break;
        case 23: cg_math<3,2,1,0>(sA,sB,sC,b0); break;
        case 24: cg_math<3,2,2,1>(sA,sB,sC,b0); break;
        case 25: cg_math<3,3,0,2>(sA,sB,sC,b0); break;
        case 26: cg_math<3,3,1,3>(sA,sB,sC,b0); break;
        case 27: cg_math<3,3,2,4>(sA,sB,sC,b0); break;
        case 28: cg_math<3,3,3,5>(sA,sB,sC,b0); break;
        case 29: cg_math<3,4,1,6>(sA,sB,sC,b0); break;
        case 30: cg_math<3,4,2,7>(sA,sB,sC,b0); break;
        case 31: cg_math<3,4,3,8>(sA,sB,sC,b0); break;
        case 32: cg_math<3,4,4,9>(sA,sB,sC,b0); break;
        case 33: cg_math<4,2,2,0>(sA,sB,sC,b0); break;
        case 34: cg_math<4,3,1,1>(sA,sB,sC,b0); break;
        case 35: cg_math<4,3,2,2>(sA,sB,sC,b0); break;
        case 36: cg_math<4,3,3,3>(sA,sB,sC,b0); break;
        case 37: cg_math<4,4,0,4>(sA,sB,sC,b0); break;
        case 38: cg_math<4,4,1,5>(sA,sB,sC,b0); break;
        case 39: cg_math<4,4,2,6>(sA,sB,sC,b0); break;
        case 40: cg_math<4,4,3,7>(sA,sB,sC,b0); break;
        case 41: cg_math<4,4,4,8>(sA,sB,sC,b0); break;
    }
}

// ---------------- fold BN scale into pre-broadcast weights ------------------
__global__ void k_prepw(const float* __restrict__ W) {
    int gid = blockIdx.x * 256 + threadIdx.x;   // 672*256 == 172032 exactly
    int cgl = gid >> 4;
    int o   = gid & 15;
    int l = 0;
    while (l < 4 && cgl >= c_chanbase[l + 1]) ++l;
    int cl = cgl - c_chanbase[l];
    float var   = g_sumsq[cgl] * (1.0f / (256.0f * (float)(2 * l + 1)));
    float scale = 1.0f / (sqrtf(var) + 1e-5f);
    int widx = (c_woff[l] + o * c_TFF[l] + cl) * 2;
    float wr = W[widx + 0] * scale;
    float wi = W[widx + 1] * scale;
    g_W2[gid] = make_float4(wr, wr, -wi, wi);   // {wx, wx, -wy, wy}
}

// -------------------- complex GEMM via packed f32x2 + smem W ----------------
// 460 blocks (128 ch x 256 n x 16 o each), thread tile 4n x 8o (32 u64 accs),
// single co-resident wave at ~4 blocks/SM (reg-limited, no min-blocks clamp).
// Inner loop per channel: 2 X LDG.128 + 8 warp-uniform LDS.128 + 4 swaps +
// 64 fma.rn.f32x2 (FMA:LDS ratio 8, twice r6's).
__global__ void __launch_bounds__(128) k_gemm() {
    __shared__ float4 sW[2048];                    // [128 ch][16 o] = 32KB

    int bid = blockIdx.x;
    int l = 0;
    while (l < 4 && bid >= c_itemPrefix[l + 1]) ++l;
    int rel    = bid - c_itemPrefix[l];
    int Nl     = c_N[l];
    int ntiles = Nl >> 8;                          // 256-n tiles
    int ntile  = rel % ntiles;
    int ks     = rel / ntiles;
    int c0     = ks << 7;                          // 128 channels per slice

    // stage W tile (2048 float4 = 32KB), once
    const float4* __restrict__ Wg = g_W2 + (c_chanbase[l] + c0) * 16;
    #pragma unroll
    for (int e = threadIdx.x; e < 2048; e += 128)
        sW[e] = Wg[e];
    __syncthreads();

    int og = (threadIdx.x >> 6) << 3;              // output base: 0 or 8
    int n0 = (ntile << 8) + ((threadIdx.x & 63) << 2);   // 4 n per thread

    const ulonglong2* __restrict__ X =
        (const ulonglong2*)(g_X + (size_t)(c_xbase[l] + c0 * Nl + n0));
    const ulonglong2* __restrict__ Ws = ((const ulonglong2*)sW) + og;
    int xstride = Nl >> 1;                         // row stride in ulonglong2

    uint64_t acc[8][4];                            // [o][n] packed (ar,ai)
    #pragma unroll
    for (int o = 0; o < 8; ++o)
        #pragma unroll
        for (int nn = 0; nn < 4; ++nn) acc[o][nn] = 0ULL;

    #pragma unroll 2
    for (int cc = 0; cc < 128; ++cc) {
        ulonglong2 v0 = __ldg(X + cc * xstride);
        ulonglong2 v1 = __ldg(X + cc * xstride + 1);
        uint64_t x0 = v0.x, x1 = v0.y, x2 = v1.x, x3 = v1.y;
        uint64_t s0 = swap32(x0), s1 = swap32(x1);
        uint64_t s2 = swap32(x2), s3 = swap32(x3);
        const ulonglong2* wrow = Ws + cc * 16;
        #pragma unroll
        for (int oo = 0; oo < 8; ++oo) {
            ulonglong2 w = wrow[oo];               // LDS.128 broadcast
            fma2(acc[oo][0], w.x, x0);
            fma2(acc[oo][0], w.y, s0);
            fma2(acc[oo][1], w.x, x1);
            fma2(acc[oo][1], w.y, s1);
            fma2(acc[oo][2], w.x, x2);
            fma2(acc[oo][2], w.y, s2);
            fma2(acc[oo][3], w.x, x3);
            fma2(acc[oo][3], w.y, s3);
        }
    }

    float* P = g_partial + c_pbase2[l] + ks * (Nl << 5);
    #pragma unroll
    for (int oo = 0; oo < 8; ++oo) {
        int o = og + oo;
        float2 a0 = unpack2(acc[oo][0]);
        float2 a1 = unpack2(acc[oo][1]);
        float2 a2 = unpack2(acc[oo][2]);
        float2 a3 = unpack2(acc[oo][3]);
        float* dst = P + (size_t)(o * Nl + n0) * 2;
        *(float4*)(dst)     = make_float4(a0.x, a0.y, a1.x, a1.y);
        *(float4*)(dst + 4) = make_float4(a2.x, a2.y, a3.x, a3.y);
    }
}

// -------------------- reduce K-slices into harness layout (float4) ----------
__global__ void k_reduce(float* __restrict__ out) {
    int p4 = blockIdx.x * 256 + threadIdx.x;   // 200*256 == 51200 float4 groups
    int p  = p4 << 2;
    int l = 0;
    while (l < 4 && p >= c_pobase[l + 1]) ++l;
    int rem = p - c_pobase[l];
    int Nl  = c_N[l];
    int stride4 = Nl << 3;                     // (Nl<<5)/4 in float4 units
    const float4* P = (const float4*)(g_partial + c_pbase2[l]) + (rem >> 2);
    int ns = c_splits[l];
    float4 s = make_float4(0.f, 0.f, 0.f, 0.f);
    #pragma unroll 4
    for (int ks = 0; ks < ns; ++ks) {
        float4 v = __ldg(P + ks * stride4);
        s.x += v.x; s.y += v.y; s.z += v.z; s.w += v.w;
    }
    // rem = (o*Nl + n)*2 + ri; group covers (n, ri=0/1) and (n+1, ri=0/1)
    int on = rem >> 1;
    int o  = on / Nl;
    int n  = on - o * Nl;
    int M  = n >> 8, b = n & 255;
    int row = c_inoff[l] + o * (2 * l + 1) + M;
    *(float2*)(out + (size_t)b * 800 + row * 2)       = make_float2(s.x, s.y);
    *(float2*)(out + (size_t)(b + 1) * 800 + row * 2) = make_float2(s.z, s.w);
}

// ---------------------------------------------------------------------------
extern "C" void kernel_launch(void* const* d_in, const int* in_sizes, int n_in,
                              void* d_out, int out_size) {
    const float* Fs = (const float*)d_in[0];
    const float* W  = (const float*)d_in[1];
    if (n_in >= 2 && in_sizes[0] == 344064) {   // defensive: metadata order
        W  = (const float*)d_in[0];
        Fs = (const float*)d_in[1];
    }
    float* out = (float*)d_out;

    k_init  <<<42,  256>>>();
    k_cg    <<<672, 256>>>(Fs);
    k_prepw <<<672, 256>>>(W);
    k_gemm  <<<460, 128>>>();
    k_reduce<<<200, 256>>>(out);
}

// round 15
// speedup vs baseline: 1.2477x; 1.2337x over previous
#include <cuda_runtime.h>
#include <math.h>
#include <stdint.h>

// ---------------------------------------------------------------------------
// CG tensor-product network (LMAX=4, taus=16, t_O=16), B=256.
// Round-6 champion configuration + float4 k_reduce:
// k_init -> k_cg (templated, sorted heavy-first) -> k_prepw ->
// k_gemm (f32x2, 128-ch K-slices x 128-n tiles, 920 blocks, 6/SM, 32KB W
// staged once, barrier-free) -> k_reduce (float4, 15MB partials).
// ---------------------------------------------------------------------------

#define NT 42

__constant__ int c_tL1[NT] = {0,1,2,3,4, 1,1,2,2,3,3,4,4, 1,2,2,2,3,3,3,4,4,4,
                              2,2,3,3,3,3,4,4,4,4, 2,3,3,3,4,4,4,4,4};
__constant__ int c_tL2[NT] = {0,1,2,3,4, 0,1,1,2,2,3,3,4, 1,0,1,2,1,2,3,2,3,4,
                              1,2,0,1,2,3,1,2,3,4, 2,1,2,3,0,1,2,3,4};
// triples sorted by descending per-thread cost (D*D2) for load balance
__constant__ int c_order[NT] = {41,32,36,40,28,31,22,33,35,39,
                                19,21,24,27,30,12,34,38,16,18,
                                20,10,11,23,26,29, 8, 9,13,15,
                                17, 4, 6, 7,37, 3,25, 2,14, 1,
                                 5, 0};

__constant__ int c_chanbase[6]   = {0,1280,3328,5888,8448,10752};
__constant__ int c_N[5]          = {256,768,1280,1792,2304};
__constant__ int c_inoff[5]      = {0,16,64,144,256};
__constant__ int c_TFF[5]        = {1280,2048,2560,2560,2304};
__constant__ int c_woff[5]       = {0,20480,53248,94208,135168};
__constant__ int c_pobase[6]     = {0,8192,32768,73728,131072,204800};
__constant__ int c_xbase[5]      = {0,327680,1900544,5177344,9764864};

// uniform-cost GEMM decomposition: 128-channel K-slices, 128-n tiles
__constant__ int c_itemPrefix[6] = {0,20,116,316,596,920};
__constant__ int c_splits[5]     = {10,16,20,20,18};
__constant__ int c_pbase2[6]     = {0,81920,475136,1294336,2441216,3768320};

// scratch (static __device__ globals: sanctioned no-alloc scratch path)
__device__ float  g_cg[NT * 81];
__device__ float  g_sumsq[10752];
__device__ float2 g_X[15073280];        // interleaved (xr, xi), [c][m*256+b]
__device__ float4 g_W2[172032];         // [chan][o] -> {wx, wx, -wy, wy}
__device__ float  g_partial[3768320];   // per-l K-slice partials, [o][n][ri]

// -------------------------- f32x2 helpers ----------------------------------
__device__ __forceinline__ void fma2(uint64_t& d, uint64_t a, uint64_t b) {
    asm("fma.rn.f32x2 %0, %1, %2, %0;" : "+l"(d) : "l"(a), "l"(b));
}
__device__ __forceinline__ uint64_t swap32(uint64_t v) {
    uint32_t lo = (uint32_t)v, hi = (uint32_t)(v >> 32);
    uint64_t r;
    asm("mov.b64 %0, {%1, %2};" : "=l"(r) : "r"(hi), "r"(lo));
    return r;
}
__device__ __forceinline__ float2 unpack2(uint64_t v) {
    float2 f;
    asm("mov.b64 {%0, %1}, %2;" : "=f"(f.x), "=f"(f.y) : "l"(v));
    return f;
}

// -------------------------- CG coefficients --------------------------------
__device__ double dfact(int n) {
    double r = 1.0;
    for (int i = 2; i <= n; ++i) r *= (double)i;
    return r;
}

__device__ double cg_coef(int j1, int m1, int j2, int m2, int j, int m) {
    if (m1 + m2 != m) return 0.0;
    double pref = sqrt((2.0 * j + 1.0) * dfact(j + j1 - j2) * dfact(j - j1 + j2)
                       * dfact(j1 + j2 - j) / dfact(j1 + j2 + j + 1));
    pref *= sqrt(dfact(j + m) * dfact(j - m) * dfact(j1 - m1) * dfact(j1 + m1)
               * dfact(j2 - m2) * dfact(j2 + m2));
    double s = 0.0;
    for (int k = 0; k <= j1 + j2 - j; ++k) {
        if (j1 - m1 - k < 0 || j2 + m2 - k < 0 ||
            j - j2 + m1 + k < 0 || j - j1 - m2 + k < 0) continue;
        double term = 1.0 / (dfact(k) * dfact(j1 + j2 - j - k) * dfact(j1 - m1 - k)
                           * dfact(j2 + m2 - k) * dfact(j - j2 + m1 + k)
                           * dfact(j - j1 - m2 + k));
        s += (k & 1) ? -term : term;
    }
    return pref * s;
}

__constant__ int c_tLfull[NT] = {0,0,0,0,0, 1,1,1,1,1,1,1,1, 2,2,2,2,2,2,2,2,2,2,
                                 3,3,3,3,3,3,3,3,3,3, 4,4,4,4,4,4,4,4,4};

__global__ void k_init() {
    int t = blockIdx.x;                        // 42 blocks, 256 threads
    g_sumsq[t * 256 + threadIdx.x] = 0.0f;     // 42*256 == 10752 exactly
    int l = c_tLfull[t], l1 = c_tL1[t], l2 = c_tL2[t];
    int s = l1 + l2 - l;
    for (int e = threadIdx.x; e < 81; e += blockDim.x) {
        int M = e / 9, M1 = e % 9;
        float v = 0.0f;
        if (M <= 2 * l && M1 <= 2 * l1) {
            int M2 = M + s - M1;
            if (M2 >= 0 && M2 <= 2 * l2)
                v = (float)cg_coef(l1, M1 - l1, l2, M2 - l2, l, M - l);
        }
        g_cg[t * 81 + e] = v;
    }
}

// -------------------- CG tensor product (templated math) --------------------
__device__ __forceinline__ int sidx(int ri, int ch, int m, int lane) {
    return ((ri * 16 + ch) * 9 + m) * 16 + lane;
}

template <int L, int L1, int L2, int RANK>
__device__ __forceinline__ void cg_math(const float* __restrict__ sA,
                                        const float* __restrict__ sB,
                                        const float* __restrict__ sC,
                                        int b0) {
    constexpr int D  = 2 * L + 1;
    constexpr int D1 = 2 * L1 + 1;
    constexpr int D2 = 2 * L2 + 1;
    constexpr int S  = L1 + L2 - L;
    constexpr int XB[5] = {0, 327680, 1900544, 5177344, 9764864};
    constexpr int CB[5] = {0, 1280, 3328, 5888, 8448};
    constexpr int NL = 256 * D;

    const int lane = threadIdx.x & 15;   // b within chunk
    const int j    = threadIdx.x >> 4;   // second channel index

    float br[D2], bi[D2];
    #pragma unroll
    for (int m = 0; m < D2; ++m) {
        br[m] = sB[sidx(0, j, m, lane)];
        bi[m] = sB[sidx(1, j, m, lane)];
    }

    for (int i = 0; i < 16; ++i) {
        float ar[D1], ai[D1];
        #pragma unroll
        for (int m = 0; m < D1; ++m) {
            ar[m] = sA[sidx(0, i, m, lane)];
            ai[m] = sA[sidx(1, i, m, lane)];
        }
        int chan = RANK * 256 + i * 16 + j;
        int xb   = XB[L] + chan * NL + b0 + lane;
        float ss = 0.0f;
        #pragma unroll
        for (int M = 0; M < D; ++M) {
            float fr = 0.0f, fi = 0.0f;
            #pragma unroll
            for (int M1 = 0; M1 < D1; ++M1) {
                int M2 = M + S - M1;
                if (M2 >= 0 && M2 <= 2 * L2) {
                    float cg = sC[M * 9 + M1];
                    fr += cg * (ar[M1] * br[M2] - ai[M1] * bi[M2]);
                    fi += cg * (ar[M1] * bi[M2] + ai[M1] * br[M2]);
                }
            }
            g_X[xb + M * 256] = make_float2(fr, fi);
            ss += fr * fr + fi * fi;
        }
        #pragma unroll
        for (int off = 8; off; off >>= 1)
            ss += __shfl_xor_sync(0xffffffffu, ss, off);
        if (lane == 0) atomicAdd(&g_sumsq[CB[L] + chan], ss);
    }
}

// grid: 42 triples * 16 b-chunks; block 256 = (16 j) x (16 b)
__global__ void __launch_bounds__(256) k_cg(const float* __restrict__ Fs) {
    int t  = c_order[blockIdx.x >> 4];   // heavy triples first (r6 config)
    int b0 = (blockIdx.x & 15) << 4;
    int l1 = c_tL1[t], l2 = c_tL2[t];
    int d1 = 2 * l1 + 1, d2 = 2 * l2 + 1;

    __shared__ float sA[2 * 16 * 9 * 16];
    __shared__ float sB[2 * 16 * 9 * 16];
    __shared__ float sC[81];

    for (int e = threadIdx.x; e < 81; e += 256) sC[e] = g_cg[t * 81 + e];

    int off1 = c_inoff[l1], off2 = c_inoff[l2];
    int nA = 32 * d1;
    for (int e = threadIdx.x; e < 16 * nA; e += 256) {
        int bb = e / nA; int r = e - bb * nA;
        int ri = r & 1;  int cm = r >> 1;
        int ch = cm / d1; int mm = cm - ch * d1;
        sA[sidx(ri, ch, mm, bb)] = Fs[(b0 + bb) * 800 + (off1 + ch * d1 + mm) * 2 + ri];
    }
    int nB = 32 * d2;
    for (int e = threadIdx.x; e < 16 * nB; e += 256) {
        int bb = e / nB; int r = e - bb * nB;
        int ri = r & 1;  int cm = r >> 1;
        int ch = cm / d2; int mm = cm - ch * d2;
        sB[sidx(ri, ch, mm, bb)] = Fs[(b0 + bb) * 800 + (off2 + ch * d2 + mm) * 2 + ri];
    }
    __syncthreads();

    switch (t) {
        case  0: cg_math<0,0,0,0>(sA,sB,sC,b0); break;
        case  1: cg_math<0,1,1,1>(sA,sB,sC,b0); break;
        case  2: cg_math<0,2,2,2>(sA,sB,sC,b0); break;
        case  3: cg_math<0,3,3,3>(sA,sB,sC,b0); break;
        case  4: cg_math<0,4,4,4>(sA,sB,sC,b0); break;
        case  5: cg_math<1,1,0,0>(sA,sB,sC,b0); break;
        case  6: cg_math<1,1,1,1>(sA,sB,sC,b0); break;
        case  7: cg_math<1,2,1,2>(sA,sB,sC,b0); break;
        case  8: cg_math<1,2,2,3>(sA,sB,sC,b0); break;
        case  9: cg_math<1,3,2,4>(sA,sB,sC,b0); break;
        case 10: cg_math<1,3,3,5>(sA,sB,sC,b0); break;
        case 11: cg_math<1,4,3,6>(sA,sB,sC,b0); break;
        case 12: cg_math<1,4,4,7>(sA,sB,sC,b0); break;
        case 13: cg_math<2,1,1,0>(sA,sB,sC,b0); break;
        case 14: cg_math<2,2,0,1>(sA,sB,sC,b0); break;
        case 15: cg_math<2,2,1,2>(sA,sB,sC,b0); break;
        case 16: cg_math<2,2,2,3>(sA,sB,sC,b0); break;
        case 17: cg_math<2,3,1,4>(sA,sB,sC,b0); break;
        case 18: cg_math<2,3,2,5>(sA,sB,sC,b0); break;
        case 19: cg_math<2,3,3,6>(sA,sB,sC,b0); break;
        case 20: cg_math<2,4,2,7>(sA,sB,sC,b0); break;
        case 21: cg_math<2,4,3,8>(sA,sB,sC,b0); break;
        case 22: cg_math<2,4,4,9>(sA,sB,sC,b0); break;
        case 23: cg_math<3,2,1,0>(sA,sB,sC,b0); break;
        case 24: cg_math<3,2,2,1>(sA,sB,sC,b0); break;
        case 25: cg_math<3,3,0,2>(sA,sB,sC,b0); break;
        case 26: cg_math<3,3,1,3>(sA,sB,sC,b0); break;
        case 27: cg_math<3,3,2,4>(sA,sB,sC,b0); break;
        case 28: cg_math<3,3,3,5>(sA,sB,sC,b0); break;
        case 29: cg_math<3,4,1,6>(sA,sB,sC,b0); break;
        case 30: cg_math<3,4,2,7>(sA,sB,sC,b0); break;
        case 31: cg_math<3,4,3,8>(sA,sB,sC,b0); break;
        case 32: cg_math<3,4,4,9>(sA,sB,sC,b0); break;
        case 33: cg_math<4,2,2,0>(sA,sB,sC,b0); break;
        case 34: cg_math<4,3,1,1>(sA,sB,sC,b0); break;
        case 35: cg_math<4,3,2,2>(sA,sB,sC,b0); break;
        case 36: cg_math<4,3,3,3>(sA,sB,sC,b0); break;
        case 37: cg_math<4,4,0,4>(sA,sB,sC,b0); break;
        case 38: cg_math<4,4,1,5>(sA,sB,sC,b0); break;
        case 39: cg_math<4,4,2,6>(sA,sB,sC,b0); break;
        case 40: cg_math<4,4,3,7>(sA,sB,sC,b0); break;
        case 41: cg_math<4,4,4,8>(sA,sB,sC,b0); break;
    }
}

// ---------------- fold BN scale into pre-broadcast weights ------------------
__global__ void k_prepw(const float* __restrict__ W) {
    int gid = blockIdx.x * 256 + threadIdx.x;   // 672*256 == 172032 exactly
    int cgl = gid >> 4;
    int o   = gid & 15;
    int l = 0;
    while (l < 4 && cgl >= c_chanbase[l + 1]) ++l;
    int cl = cgl - c_chanbase[l];
    float var   = g_sumsq[cgl] * (1.0f / (256.0f * (float)(2 * l + 1)));
    float scale = 1.0f / (sqrtf(var) + 1e-5f);
    int widx = (c_woff[l] + o * c_TFF[l] + cl) * 2;
    float wr = W[widx + 0] * scale;
    float wi = W[widx + 1] * scale;
    g_W2[gid] = make_float4(wr, wr, -wi, wi);   // {wx, wx, -wy, wy}
}

// -------------------- complex GEMM via packed f32x2 + smem W ----------------
// 920 identical blocks (128 ch x 128 n x 16 o), 6 blocks/SM (32KB smem).
// r6 champion config: W staged once, barrier-free mainloop:
// 1 X LDG.128 + 8 warp-uniform LDS.128 + 2 swaps + 32 fma.rn.f32x2 / ch.
__global__ void __launch_bounds__(128, 6) k_gemm() {
    __shared__ float4 sW[2048];                    // [128 ch][16 o] = 32KB

    int bid = blockIdx.x;
    int l = 0;
    while (l < 4 && bid >= c_itemPrefix[l + 1]) ++l;
    int rel    = bid - c_itemPrefix[l];
    int Nl     = c_N[l];
    int ntiles = Nl >> 7;
    int ntile  = rel % ntiles;
    int ks     = rel / ntiles;
    int c0     = ks << 7;                          // 128 channels per slice

    // stage W tile (2048 float4 = 32KB), once
    const float4* __restrict__ Wg = g_W2 + (c_chanbase[l] + c0) * 16;
    #pragma unroll
    for (int e = threadIdx.x; e < 2048; e += 128)
        sW[e] = Wg[e];
    __syncthreads();

    int og = (threadIdx.x >> 6) << 3;              // output base: 0 or 8
    int n0 = (ntile << 7) + ((threadIdx.x & 63) << 1);

    const float2* __restrict__ X = g_X + (size_t)(c_xbase[l] + c0 * Nl + n0);
    const ulonglong2* __restrict__ Ws = ((const ulonglong2*)sW) + og;

    uint64_t acc0[8], acc1[8];                     // (ar,ai) for n0, n0+1
    #pragma unroll
    for (int o = 0; o < 8; ++o) { acc0[o] = 0ULL; acc1[o] = 0ULL; }

    #pragma unroll 4
    for (int cc = 0; cc < 128; ++cc) {
        ulonglong2 xv = __ldg((const ulonglong2*)(X + cc * Nl));
        uint64_t x0 = xv.x, x1 = xv.y;
        uint64_t x0s = swap32(x0), x1s = swap32(x1);
        const ulonglong2* wrow = Ws + cc * 16;
        #pragma unroll
        for (int oo = 0; oo < 8; ++oo) {
            ulonglong2 w = wrow[oo];               // LDS.128 broadcast
            fma2(acc0[oo], w.x, x0);
            fma2(acc0[oo], w.y, x0s);
            fma2(acc1[oo], w.x, x1);
            fma2(acc1[oo], w.y, x1s);
        }
    }

    float* P = g_partial + c_pbase2[l] + ks * (Nl << 5);
    #pragma unroll
    for (int oo = 0; oo < 8; ++oo) {
        int o = og + oo;
        float2 a0 = unpack2(acc0[oo]);
        float2 a1 = unpack2(acc1[oo]);
        *(float4*)(P + (size_t)(o * Nl + n0) * 2) =
            make_float4(a0.x, a0.y, a1.x, a1.y);
    }
}

// -------------------- reduce K-slices into harness layout (float4) ----------
__global__ void k_reduce(float* __restrict__ out) {
    int p4 = blockIdx.x * 256 + threadIdx.x;   // 200*256 == 51200 float4 groups
    int p  = p4 << 2;
    int l = 0;
    while (l < 4 && p >= c_pobase[l + 1]) ++l;
    int rem = p - c_pobase[l];
    int Nl  = c_N[l];
    int stride4 = Nl << 3;                     // (Nl<<5)/4 in float4 units
    const float4* P = (const float4*)(g_partial + c_pbase2[l]) + (rem >> 2);
    int ns = c_splits[l];
    float4 s = make_float4(0.f, 0.f, 0.f, 0.f);
    #pragma unroll 4
    for (int ks = 0; ks < ns; ++ks) {
        float4 v = __ldg(P + ks * stride4);
        s.x += v.x; s.y += v.y; s.z += v.z; s.w += v.w;
    }
    // rem = (o*Nl + n)*2 + ri; group covers (n, ri=0/1) and (n+1, ri=0/1)
    int on = rem >> 1;
    int o  = on / Nl;
    int n  = on - o * Nl;
    int M  = n >> 8, b = n & 255;
    int row = c_inoff[l] + o * (2 * l + 1) + M;
    *(float2*)(out + (size_t)b * 800 + row * 2)       = make_float2(s.x, s.y);
    *(float2*)(out + (size_t)(b + 1) * 800 + row * 2) = make_float2(s.z, s.w);
}

// ---------------------------------------------------------------------------
extern "C" void kernel_launch(void* const* d_in, const int* in_sizes, int n_in,
                              void* d_out, int out_size) {
    const float* Fs = (const float*)d_in[0];
    const float* W  = (const float*)d_in[1];
    if (n_in >= 2 && in_sizes[0] == 344064) {   // defensive: metadata order
        W  = (const float*)d_in[0];
        Fs = (const float*)d_in[1];
    }
    float* out = (float*)d_out;

    k_init  <<<42,  256>>>();
    k_cg    <<<672, 256>>>(Fs);
    k_prepw <<<672, 256>>>(W);
    k_gemm  <<<920, 128>>>();
    k_reduce<<<200, 256>>>(out);
}